// round 1
// baseline (speedup 1.0000x reference)
#include <cuda_runtime.h>
#include <cstdint>

#define E_ 8
#define D_ 512
#define F_ 2048
#define N_ 4096

// ---------------- scratch (no allocations allowed) ----------------
__device__ int   g_counts[E_];
__device__ int   g_offsets[E_];
__device__ int   g_expert[N_];
__device__ int   g_pos[N_];
__device__ int   g_row2tok[N_];
__device__ float g_H[(size_t)N_ * F_];   // 32 MB intermediate

// ---------------- init ----------------
__global__ void init_kernel() {
    int t = threadIdx.x;
    if (t < E_) g_counts[t] = 0;
}

// ---------------- gate: one warp per token ----------------
__global__ void gate_kernel(const float* __restrict__ x,
                            const float* __restrict__ Wg,
                            const float* __restrict__ bg) {
    int warp = (blockIdx.x * blockDim.x + threadIdx.x) >> 5;
    int lane = threadIdx.x & 31;
    if (warp >= N_) return;
    const float* xr = x + (size_t)warp * D_;

    float acc[E_];
#pragma unroll
    for (int e = 0; e < E_; e++) acc[e] = 0.f;

    for (int d = lane; d < D_; d += 32) {
        float xv = xr[d];
        const float4* w = reinterpret_cast<const float4*>(Wg + (size_t)d * E_);
        float4 w0 = w[0], w1 = w[1];
        acc[0] += xv * w0.x; acc[1] += xv * w0.y;
        acc[2] += xv * w0.z; acc[3] += xv * w0.w;
        acc[4] += xv * w1.x; acc[5] += xv * w1.y;
        acc[6] += xv * w1.z; acc[7] += xv * w1.w;
    }
#pragma unroll
    for (int off = 16; off > 0; off >>= 1) {
#pragma unroll
        for (int e = 0; e < E_; e++)
            acc[e] += __shfl_down_sync(0xFFFFFFFFu, acc[e], off);
    }
    if (lane == 0) {
        float best = acc[0] + bg[0];
        int bi = 0;
#pragma unroll
        for (int e = 1; e < E_; e++) {
            float v = acc[e] + bg[e];
            if (v > best) { best = v; bi = e; }   // first-occurrence argmax
        }
        int p = atomicAdd(&g_counts[bi], 1);
        g_expert[warp] = bi;
        g_pos[warp]    = p;
    }
}

// ---------------- exclusive scan of 8 counts ----------------
__global__ void scan_kernel() {
    if (threadIdx.x == 0) {
        int s = 0;
#pragma unroll
        for (int e = 0; e < E_; e++) { g_offsets[e] = s; s += g_counts[e]; }
    }
}

// ---------------- assign compacted rows ----------------
__global__ void assign_kernel() {
    int t = blockIdx.x * blockDim.x + threadIdx.x;
    if (t >= N_) return;
    int r = g_offsets[g_expert[t]] + g_pos[t];
    g_row2tok[r] = t;
}

// ---------------- GEMM1: H = relu(X[gather] @ W1[e] + b1[e]) ----------------
// BM=128 BN=128 BK=16, 256 threads, 8x8 micro-tile. K = D_ = 512.
__global__ __launch_bounds__(256)
void gemm1_kernel(const float* __restrict__ x,
                  const float* __restrict__ W1,
                  const float* __restrict__ b1) {
    const int e   = blockIdx.z;
    const int cnt = g_counts[e];
    const int m0  = blockIdx.y * 128;
    if (m0 >= cnt) return;
    const int off = g_offsets[e];
    const int n0  = blockIdx.x * 128;

    __shared__ float As[16][128];
    __shared__ float Bs[16][128];

    const float* Wb = W1 + (size_t)e * D_ * F_;
    const int tid = threadIdx.x;

    // A gather setup: thread loads float4 v=tid and v=tid+256
    const int rowA0 = tid >> 2,          kk40 = (tid & 3) * 4;
    const int rowA1 = (tid + 256) >> 2,  kk41 = ((tid + 256) & 3) * 4;
    int rg0 = m0 + rowA0; if (rg0 > cnt - 1) rg0 = cnt - 1;
    int rg1 = m0 + rowA1; if (rg1 > cnt - 1) rg1 = cnt - 1;
    const float* xrow0 = x + (size_t)g_row2tok[off + rg0] * D_ + kk40;
    const float* xrow1 = x + (size_t)g_row2tok[off + rg1] * D_ + kk41;

    // B load setup
    const int kB = tid >> 5;
    const int nB = (tid & 31) * 4;

    const int ty = tid >> 4, tx = tid & 15;

    float acc[8][8];
#pragma unroll
    for (int i = 0; i < 8; i++)
#pragma unroll
        for (int j = 0; j < 8; j++) acc[i][j] = 0.f;

    for (int k0 = 0; k0 < D_; k0 += 16) {
        float4 a0 = *reinterpret_cast<const float4*>(xrow0 + k0);
        float4 a1 = *reinterpret_cast<const float4*>(xrow1 + k0);
        float4 bz0 = *reinterpret_cast<const float4*>(Wb + (size_t)(k0 + kB) * F_ + n0 + nB);
        float4 bz1 = *reinterpret_cast<const float4*>(Wb + (size_t)(k0 + kB + 8) * F_ + n0 + nB);
        __syncthreads();
        As[kk40 + 0][rowA0] = a0.x; As[kk40 + 1][rowA0] = a0.y;
        As[kk40 + 2][rowA0] = a0.z; As[kk40 + 3][rowA0] = a0.w;
        As[kk41 + 0][rowA1] = a1.x; As[kk41 + 1][rowA1] = a1.y;
        As[kk41 + 2][rowA1] = a1.z; As[kk41 + 3][rowA1] = a1.w;
        *reinterpret_cast<float4*>(&Bs[kB][nB])     = bz0;
        *reinterpret_cast<float4*>(&Bs[kB + 8][nB]) = bz1;
        __syncthreads();
#pragma unroll
        for (int k = 0; k < 16; k++) {
            float ra[8], rb[8];
            *reinterpret_cast<float4*>(ra)     = *reinterpret_cast<float4*>(&As[k][ty * 8]);
            *reinterpret_cast<float4*>(ra + 4) = *reinterpret_cast<float4*>(&As[k][ty * 8 + 4]);
            *reinterpret_cast<float4*>(rb)     = *reinterpret_cast<float4*>(&Bs[k][tx * 8]);
            *reinterpret_cast<float4*>(rb + 4) = *reinterpret_cast<float4*>(&Bs[k][tx * 8 + 4]);
#pragma unroll
            for (int i = 0; i < 8; i++)
#pragma unroll
                for (int j = 0; j < 8; j++)
                    acc[i][j] += ra[i] * rb[j];
        }
    }

    // epilogue: bias + relu + store to H
    const float* b1e = b1 + (size_t)e * F_;
#pragma unroll
    for (int i = 0; i < 8; i++) {
        int r = m0 + ty * 8 + i;
        if (r >= cnt) continue;
        float* Hrow = g_H + (size_t)(off + r) * F_ + n0 + tx * 8;
#pragma unroll
        for (int j = 0; j < 8; j += 4) {
            float4 v;
            float bv0 = b1e[n0 + tx * 8 + j + 0];
            float bv1 = b1e[n0 + tx * 8 + j + 1];
            float bv2 = b1e[n0 + tx * 8 + j + 2];
            float bv3 = b1e[n0 + tx * 8 + j + 3];
            v.x = fmaxf(acc[i][j + 0] + bv0, 0.f);
            v.y = fmaxf(acc[i][j + 1] + bv1, 0.f);
            v.z = fmaxf(acc[i][j + 2] + bv2, 0.f);
            v.w = fmaxf(acc[i][j + 3] + bv3, 0.f);
            *reinterpret_cast<float4*>(Hrow + j) = v;
        }
    }
}

// ---------------- GEMM2: out[tok] = H @ W2[e] + b2[e] ----------------
// BM=128 BN=128 BK=16. K = F_ = 2048, N-dim = D_ = 512 (4 tiles).
__global__ __launch_bounds__(256)
void gemm2_kernel(const float* __restrict__ W2,
                  const float* __restrict__ b2,
                  float* __restrict__ out) {
    const int e   = blockIdx.z;
    const int cnt = g_counts[e];
    const int m0  = blockIdx.y * 128;
    if (m0 >= cnt) return;
    const int off = g_offsets[e];
    const int n0  = blockIdx.x * 128;

    __shared__ float As[16][128];
    __shared__ float Bs[16][128];

    const float* Wb = W2 + (size_t)e * F_ * D_;
    const int tid = threadIdx.x;

    const int rowA0 = tid >> 2,          kk40 = (tid & 3) * 4;
    const int rowA1 = (tid + 256) >> 2,  kk41 = ((tid + 256) & 3) * 4;
    int rg0 = m0 + rowA0; if (rg0 > cnt - 1) rg0 = cnt - 1;
    int rg1 = m0 + rowA1; if (rg1 > cnt - 1) rg1 = cnt - 1;
    const float* hrow0 = g_H + (size_t)(off + rg0) * F_ + kk40;
    const float* hrow1 = g_H + (size_t)(off + rg1) * F_ + kk41;

    const int kB = tid >> 5;
    const int nB = (tid & 31) * 4;
    const int ty = tid >> 4, tx = tid & 15;

    float acc[8][8];
#pragma unroll
    for (int i = 0; i < 8; i++)
#pragma unroll
        for (int j = 0; j < 8; j++) acc[i][j] = 0.f;

    for (int k0 = 0; k0 < F_; k0 += 16) {
        float4 a0 = *reinterpret_cast<const float4*>(hrow0 + k0);
        float4 a1 = *reinterpret_cast<const float4*>(hrow1 + k0);
        float4 bz0 = *reinterpret_cast<const float4*>(Wb + (size_t)(k0 + kB) * D_ + n0 + nB);
        float4 bz1 = *reinterpret_cast<const float4*>(Wb + (size_t)(k0 + kB + 8) * D_ + n0 + nB);
        __syncthreads();
        As[kk40 + 0][rowA0] = a0.x; As[kk40 + 1][rowA0] = a0.y;
        As[kk40 + 2][rowA0] = a0.z; As[kk40 + 3][rowA0] = a0.w;
        As[kk41 + 0][rowA1] = a1.x; As[kk41 + 1][rowA1] = a1.y;
        As[kk41 + 2][rowA1] = a1.z; As[kk41 + 3][rowA1] = a1.w;
        *reinterpret_cast<float4*>(&Bs[kB][nB])     = bz0;
        *reinterpret_cast<float4*>(&Bs[kB + 8][nB]) = bz1;
        __syncthreads();
#pragma unroll
        for (int k = 0; k < 16; k++) {
            float ra[8], rb[8];
            *reinterpret_cast<float4*>(ra)     = *reinterpret_cast<float4*>(&As[k][ty * 8]);
            *reinterpret_cast<float4*>(ra + 4) = *reinterpret_cast<float4*>(&As[k][ty * 8 + 4]);
            *reinterpret_cast<float4*>(rb)     = *reinterpret_cast<float4*>(&Bs[k][tx * 8]);
            *reinterpret_cast<float4*>(rb + 4) = *reinterpret_cast<float4*>(&Bs[k][tx * 8 + 4]);
#pragma unroll
            for (int i = 0; i < 8; i++)
#pragma unroll
                for (int j = 0; j < 8; j++)
                    acc[i][j] += ra[i] * rb[j];
        }
    }

    // epilogue: bias + scatter to output token rows
    const float* b2e = b2 + (size_t)e * D_;
#pragma unroll
    for (int i = 0; i < 8; i++) {
        int r = m0 + ty * 8 + i;
        if (r >= cnt) continue;
        int tok = g_row2tok[off + r];
        float* orow = out + (size_t)tok * D_ + n0 + tx * 8;
#pragma unroll
        for (int j = 0; j < 8; j += 4) {
            float4 v;
            v.x = acc[i][j + 0] + b2e[n0 + tx * 8 + j + 0];
            v.y = acc[i][j + 1] + b2e[n0 + tx * 8 + j + 1];
            v.z = acc[i][j + 2] + b2e[n0 + tx * 8 + j + 2];
            v.w = acc[i][j + 3] + b2e[n0 + tx * 8 + j + 3];
            *reinterpret_cast<float4*>(orow + j) = v;
        }
    }
}

// ---------------- launch ----------------
extern "C" void kernel_launch(void* const* d_in, const int* in_sizes, int n_in,
                              void* d_out, int out_size) {
    const float* x  = (const float*)d_in[0];
    const float* Wg = (const float*)d_in[1];
    const float* bg = (const float*)d_in[2];
    const float* W1 = (const float*)d_in[3];
    const float* b1 = (const float*)d_in[4];
    const float* W2 = (const float*)d_in[5];
    const float* b2 = (const float*)d_in[6];
    float* out = (float*)d_out;

    init_kernel<<<1, 32>>>();
    gate_kernel<<<(N_ * 32) / 256, 256>>>(x, Wg, bg);
    scan_kernel<<<1, 32>>>();
    assign_kernel<<<N_ / 256, 256>>>();

    dim3 g1(F_ / 128, N_ / 128, E_);   // (16, 32, 8) — most blocks early-exit
    gemm1_kernel<<<g1, 256>>>(x, W1, b1);

    dim3 g2(D_ / 128, N_ / 128, E_);   // (4, 32, 8)
    gemm2_kernel<<<g2, 256>>>(W2, b2, out);
}

// round 2
// speedup vs baseline: 2.7232x; 2.7232x over previous
#include <cuda_runtime.h>
#include <cstdint>

#define E_ 8
#define D_ 512
#define F_ 2048
#define N_ 4096

#define BM 128
#define BN 128
#define BK 16

// ---------------- scratch (no allocations allowed) ----------------
__device__ int   g_counts[E_];
__device__ int   g_offsets[E_];
__device__ int   g_expert[N_];
__device__ int   g_pos[N_];
__device__ int   g_row2tok[N_];
__device__ __align__(16) float g_H[(size_t)N_ * F_];   // 32 MB intermediate

// ---------------- helpers ----------------
__device__ __forceinline__ int imin(int a, int b) { return a < b ? a : b; }

__device__ __forceinline__ void cp_async16(void* sm, const void* gm) {
    uint32_t s = (uint32_t)__cvta_generic_to_shared(sm);
    asm volatile("cp.async.cg.shared.global [%0], [%1], 16;" :: "r"(s), "l"(gm));
}
__device__ __forceinline__ void cp_commit() {
    asm volatile("cp.async.commit_group;");
}

__device__ __forceinline__ uint32_t f2tf(float f) {
    uint32_t r;
    asm("cvt.rna.tf32.f32 %0, %1;" : "=r"(r) : "f"(f));
    return r;
}

__device__ __forceinline__ void mma_tf32(float c[4], const uint32_t a[4], const uint32_t b[2]) {
    asm volatile(
        "mma.sync.aligned.m16n8k8.row.col.f32.tf32.tf32.f32 "
        "{%0,%1,%2,%3}, {%4,%5,%6,%7}, {%8,%9}, {%0,%1,%2,%3};"
        : "+f"(c[0]), "+f"(c[1]), "+f"(c[2]), "+f"(c[3])
        : "r"(a[0]), "r"(a[1]), "r"(a[2]), "r"(a[3]), "r"(b[0]), "r"(b[1]));
}

// ---------------- init ----------------
__global__ void init_kernel() {
    int t = threadIdx.x;
    if (t < E_) g_counts[t] = 0;
}

// ---------------- gate: one warp per token ----------------
__global__ void gate_kernel(const float* __restrict__ x,
                            const float* __restrict__ Wg,
                            const float* __restrict__ bg) {
    int warp = (blockIdx.x * blockDim.x + threadIdx.x) >> 5;
    int lane = threadIdx.x & 31;
    if (warp >= N_) return;
    const float* xr = x + (size_t)warp * D_;

    float acc[E_];
#pragma unroll
    for (int e = 0; e < E_; e++) acc[e] = 0.f;

    for (int d = lane; d < D_; d += 32) {
        float xv = xr[d];
        const float4* w = reinterpret_cast<const float4*>(Wg + (size_t)d * E_);
        float4 w0 = w[0], w1 = w[1];
        acc[0] += xv * w0.x; acc[1] += xv * w0.y;
        acc[2] += xv * w0.z; acc[3] += xv * w0.w;
        acc[4] += xv * w1.x; acc[5] += xv * w1.y;
        acc[6] += xv * w1.z; acc[7] += xv * w1.w;
    }
#pragma unroll
    for (int off = 16; off > 0; off >>= 1) {
#pragma unroll
        for (int e = 0; e < E_; e++)
            acc[e] += __shfl_down_sync(0xFFFFFFFFu, acc[e], off);
    }
    if (lane == 0) {
        float best = acc[0] + bg[0];
        int bi = 0;
#pragma unroll
        for (int e = 1; e < E_; e++) {
            float v = acc[e] + bg[e];
            if (v > best) { best = v; bi = e; }   // first-occurrence argmax
        }
        int p = atomicAdd(&g_counts[bi], 1);
        g_expert[warp] = bi;
        g_pos[warp]    = p;
    }
}

// ---------------- exclusive scan of 8 counts ----------------
__global__ void scan_kernel() {
    if (threadIdx.x == 0) {
        int s = 0;
#pragma unroll
        for (int e = 0; e < E_; e++) { g_offsets[e] = s; s += g_counts[e]; }
    }
}

// ---------------- assign compacted rows ----------------
__global__ void assign_kernel() {
    int t = blockIdx.x * blockDim.x + threadIdx.x;
    if (t >= N_) return;
    int r = g_offsets[g_expert[t]] + g_pos[t];
    g_row2tok[r] = t;
}

// =====================================================================
// GEMM1 (tensor cores, tf32): H = relu(X[gather] @ W1[e] + b1[e])
// BM=128 BN=128 BK=16, 256 thr, 8 warps (4x2), warp tile 32x64 (2x8 MMA)
// =====================================================================
__global__ __launch_bounds__(256)
void gemm1_tc(const float* __restrict__ x,
              const float* __restrict__ W1,
              const float* __restrict__ b1) {
    const int e   = blockIdx.z;
    const int cnt = g_counts[e];
    const int m0  = blockIdx.y * BM;
    if (m0 >= cnt) return;
    const int off = g_offsets[e];
    const int n0  = blockIdx.x * BN;
    const float* Wb = W1 + (size_t)e * D_ * F_;

    __shared__ __align__(16) float As[2][BM][BK + 4];   // stride 20: conflict-free A frags
    __shared__ __align__(16) float Bs[2][BK][BN + 8];   // stride 136: conflict-free B frags

    const int tid  = threadIdx.x;
    const int lane = tid & 31;
    const int warp = tid >> 5;
    const int wm   = warp >> 1;      // 0..3
    const int wn   = warp & 1;       // 0..1

    // A loader: chunk ids tid, tid+256 -> row=id>>2, kc=(id&3)*4 (row ptr const!)
    const int arow0 = tid >> 2,           akc0 = (tid & 3) * 4;
    const int arow1 = (tid + 256) >> 2,   akc1 = ((tid + 256) & 3) * 4;
    const float* ap0 = x + (size_t)g_row2tok[off + imin(m0 + arow0, cnt - 1)] * D_ + akc0;
    const float* ap1 = x + (size_t)g_row2tok[off + imin(m0 + arow1, cnt - 1)] * D_ + akc1;
    // B loader: ids tid, tid+256 -> k=id>>5, nc=(id&31)*4
    const int bk0 = tid >> 5, bnc = (tid & 31) * 4;
    const int bk1 = bk0 + 8;
    const float* bp0 = Wb + (size_t)bk0 * F_ + n0 + bnc;
    const float* bp1 = Wb + (size_t)bk1 * F_ + n0 + bnc;

    float acc[2][8][4];
#pragma unroll
    for (int i = 0; i < 2; i++)
#pragma unroll
        for (int j = 0; j < 8; j++)
#pragma unroll
            for (int q = 0; q < 4; q++) acc[i][j][q] = 0.f;

    // prologue: stage 0
    cp_async16(&As[0][arow0][akc0], ap0);
    cp_async16(&As[0][arow1][akc1], ap1);
    cp_async16(&Bs[0][bk0][bnc],    bp0);
    cp_async16(&Bs[0][bk1][bnc],    bp1);
    cp_commit();

    const int NK = D_ / BK;   // 32
    for (int it = 0; it < NK; ++it) {
        const int cur = it & 1;
        if (it + 1 < NK) {
            const int nxt = cur ^ 1;
            const int k0  = (it + 1) * BK;
            cp_async16(&As[nxt][arow0][akc0], ap0 + k0);
            cp_async16(&As[nxt][arow1][akc1], ap1 + k0);
            cp_async16(&Bs[nxt][bk0][bnc],    bp0 + (size_t)k0 * F_);
            cp_async16(&Bs[nxt][bk1][bnc],    bp1 + (size_t)k0 * F_);
            cp_commit();
            asm volatile("cp.async.wait_group 1;");
        } else {
            asm volatile("cp.async.wait_group 0;");
        }
        __syncthreads();

#pragma unroll
        for (int kk = 0; kk < 2; ++kk) {
            const int kb = kk * 8 + (lane & 3);
            uint32_t a[2][4], b[8][2];
#pragma unroll
            for (int mt = 0; mt < 2; ++mt) {
                const int r = wm * 32 + mt * 16 + (lane >> 2);
                a[mt][0] = f2tf(As[cur][r][kb]);
                a[mt][1] = f2tf(As[cur][r + 8][kb]);
                a[mt][2] = f2tf(As[cur][r][kb + 4]);
                a[mt][3] = f2tf(As[cur][r + 8][kb + 4]);
            }
#pragma unroll
            for (int nt = 0; nt < 8; ++nt) {
                const int c = wn * 64 + nt * 8 + (lane >> 2);
                b[nt][0] = f2tf(Bs[cur][kb][c]);
                b[nt][1] = f2tf(Bs[cur][kb + 4][c]);
            }
#pragma unroll
            for (int mt = 0; mt < 2; ++mt)
#pragma unroll
                for (int nt = 0; nt < 8; ++nt)
                    mma_tf32(acc[mt][nt], a[mt], b[nt]);
        }
        __syncthreads();
    }

    // epilogue: bias + relu -> g_H
    const float* b1e = b1 + (size_t)e * F_;
#pragma unroll
    for (int mt = 0; mt < 2; ++mt) {
        const int rbase = m0 + wm * 32 + mt * 16 + (lane >> 2);
#pragma unroll
        for (int half = 0; half < 2; ++half) {
            const int r = rbase + half * 8;
            if (r < cnt) {
                float* Hrow = g_H + (size_t)(off + r) * F_;
#pragma unroll
                for (int nt = 0; nt < 8; ++nt) {
                    const int c = n0 + wn * 64 + nt * 8 + (lane & 3) * 2;
                    float v0 = acc[mt][nt][half * 2 + 0] + b1e[c];
                    float v1 = acc[mt][nt][half * 2 + 1] + b1e[c + 1];
                    float2 o = make_float2(fmaxf(v0, 0.f), fmaxf(v1, 0.f));
                    *reinterpret_cast<float2*>(Hrow + c) = o;
                }
            }
        }
    }
}

// =====================================================================
// GEMM2 (tensor cores, tf32): out[tok] = H @ W2[e] + b2[e]
// =====================================================================
__global__ __launch_bounds__(256)
void gemm2_tc(const float* __restrict__ W2,
              const float* __restrict__ b2,
              float* __restrict__ out) {
    const int e   = blockIdx.z;
    const int cnt = g_counts[e];
    const int m0  = blockIdx.y * BM;
    if (m0 >= cnt) return;
    const int off = g_offsets[e];
    const int n0  = blockIdx.x * BN;
    const float* Wb = W2 + (size_t)e * F_ * D_;

    __shared__ __align__(16) float As[2][BM][BK + 4];
    __shared__ __align__(16) float Bs[2][BK][BN + 8];

    const int tid  = threadIdx.x;
    const int lane = tid & 31;
    const int warp = tid >> 5;
    const int wm   = warp >> 1;
    const int wn   = warp & 1;

    const int arow0 = tid >> 2,           akc0 = (tid & 3) * 4;
    const int arow1 = (tid + 256) >> 2,   akc1 = ((tid + 256) & 3) * 4;
    const float* ap0 = g_H + (size_t)(off + imin(m0 + arow0, cnt - 1)) * F_ + akc0;
    const float* ap1 = g_H + (size_t)(off + imin(m0 + arow1, cnt - 1)) * F_ + akc1;
    const int bk0 = tid >> 5, bnc = (tid & 31) * 4;
    const int bk1 = bk0 + 8;
    const float* bp0 = Wb + (size_t)bk0 * D_ + n0 + bnc;
    const float* bp1 = Wb + (size_t)bk1 * D_ + n0 + bnc;

    float acc[2][8][4];
#pragma unroll
    for (int i = 0; i < 2; i++)
#pragma unroll
        for (int j = 0; j < 8; j++)
#pragma unroll
            for (int q = 0; q < 4; q++) acc[i][j][q] = 0.f;

    cp_async16(&As[0][arow0][akc0], ap0);
    cp_async16(&As[0][arow1][akc1], ap1);
    cp_async16(&Bs[0][bk0][bnc],    bp0);
    cp_async16(&Bs[0][bk1][bnc],    bp1);
    cp_commit();

    const int NK = F_ / BK;   // 128
    for (int it = 0; it < NK; ++it) {
        const int cur = it & 1;
        if (it + 1 < NK) {
            const int nxt = cur ^ 1;
            const int k0  = (it + 1) * BK;
            cp_async16(&As[nxt][arow0][akc0], ap0 + k0);
            cp_async16(&As[nxt][arow1][akc1], ap1 + k0);
            cp_async16(&Bs[nxt][bk0][bnc],    bp0 + (size_t)k0 * D_);
            cp_async16(&Bs[nxt][bk1][bnc],    bp1 + (size_t)k0 * D_);
            cp_commit();
            asm volatile("cp.async.wait_group 1;");
        } else {
            asm volatile("cp.async.wait_group 0;");
        }
        __syncthreads();

#pragma unroll
        for (int kk = 0; kk < 2; ++kk) {
            const int kb = kk * 8 + (lane & 3);
            uint32_t a[2][4], b[8][2];
#pragma unroll
            for (int mt = 0; mt < 2; ++mt) {
                const int r = wm * 32 + mt * 16 + (lane >> 2);
                a[mt][0] = f2tf(As[cur][r][kb]);
                a[mt][1] = f2tf(As[cur][r + 8][kb]);
                a[mt][2] = f2tf(As[cur][r][kb + 4]);
                a[mt][3] = f2tf(As[cur][r + 8][kb + 4]);
            }
#pragma unroll
            for (int nt = 0; nt < 8; ++nt) {
                const int c = wn * 64 + nt * 8 + (lane >> 2);
                b[nt][0] = f2tf(Bs[cur][kb][c]);
                b[nt][1] = f2tf(Bs[cur][kb + 4][c]);
            }
#pragma unroll
            for (int mt = 0; mt < 2; ++mt)
#pragma unroll
                for (int nt = 0; nt < 8; ++nt)
                    mma_tf32(acc[mt][nt], a[mt], b[nt]);
        }
        __syncthreads();
    }

    // epilogue: bias + scatter to token rows
    const float* b2e = b2 + (size_t)e * D_;
#pragma unroll
    for (int mt = 0; mt < 2; ++mt) {
        const int rbase = m0 + wm * 32 + mt * 16 + (lane >> 2);
#pragma unroll
        for (int half = 0; half < 2; ++half) {
            const int r = rbase + half * 8;
            if (r < cnt) {
                const int tok = g_row2tok[off + r];
                float* orow = out + (size_t)tok * D_;
#pragma unroll
                for (int nt = 0; nt < 8; ++nt) {
                    const int c = n0 + wn * 64 + nt * 8 + (lane & 3) * 2;
                    float2 o;
                    o.x = acc[mt][nt][half * 2 + 0] + b2e[c];
                    o.y = acc[mt][nt][half * 2 + 1] + b2e[c + 1];
                    *reinterpret_cast<float2*>(orow + c) = o;
                }
            }
        }
    }
}

// ---------------- launch ----------------
extern "C" void kernel_launch(void* const* d_in, const int* in_sizes, int n_in,
                              void* d_out, int out_size) {
    const float* x  = (const float*)d_in[0];
    const float* Wg = (const float*)d_in[1];
    const float* bg = (const float*)d_in[2];
    const float* W1 = (const float*)d_in[3];
    const float* b1 = (const float*)d_in[4];
    const float* W2 = (const float*)d_in[5];
    const float* b2 = (const float*)d_in[6];
    float* out = (float*)d_out;

    init_kernel<<<1, 32>>>();
    gate_kernel<<<(N_ * 32) / 256, 256>>>(x, Wg, bg);
    scan_kernel<<<1, 32>>>();
    assign_kernel<<<N_ / 256, 256>>>();

    dim3 g1(F_ / BN, N_ / BM, E_);   // (16, 32, 8) — inactive m-tiles early-exit
    gemm1_tc<<<g1, 256>>>(x, W1, b1);

    dim3 g2(D_ / BN, N_ / BM, E_);   // (4, 32, 8)
    gemm2_tc<<<g2, 256>>>(W2, b2, out);
}

// round 3
// speedup vs baseline: 3.3357x; 1.2249x over previous
#include <cuda_runtime.h>
#include <cstdint>

#define E_ 8
#define D_ 512
#define F_ 2048
#define N_ 4096

#define BM 128
#define BN 128
#define BK 16
#define KSPLIT 2

#define W1SZ ((size_t)E_ * D_ * F_)   // 8.4M floats
#define W2SZ ((size_t)E_ * F_ * D_)
#define XSZ  ((size_t)N_ * D_)

// ---------------- scratch (no allocations allowed) ----------------
__device__ int   g_counts[E_];
__device__ int   g_offsets[E_];
__device__ int   g_expert[N_];
__device__ int   g_pos[N_];
__device__ int   g_row2tok[N_];
__device__ int   g_rowexpert[N_];
__device__ __align__(16) float g_W1t[W1SZ];            // tf32-rounded W1
__device__ __align__(16) float g_W2t[W2SZ];            // tf32-rounded W2
__device__ __align__(16) float g_xt[XSZ];              // tf32-rounded x
__device__ __align__(16) float g_H[(size_t)N_ * F_];   // tf32-rounded hidden
__device__ __align__(16) float g_part[KSPLIT][(size_t)N_ * D_];

// ---------------- helpers ----------------
__device__ __forceinline__ int imin(int a, int b) { return a < b ? a : b; }

__device__ __forceinline__ void cp_async16(void* sm, const void* gm) {
    uint32_t s = (uint32_t)__cvta_generic_to_shared(sm);
    asm volatile("cp.async.cg.shared.global [%0], [%1], 16;" :: "r"(s), "l"(gm));
}
__device__ __forceinline__ void cp_commit() {
    asm volatile("cp.async.commit_group;");
}

__device__ __forceinline__ float f2tf(float f) {
    uint32_t r;
    asm("cvt.rna.tf32.f32 %0, %1;" : "=r"(r) : "f"(f));
    return __uint_as_float(r);
}

__device__ __forceinline__ void mma_tf32(float c[4], const uint32_t a[4], const uint32_t b[2]) {
    asm volatile(
        "mma.sync.aligned.m16n8k8.row.col.f32.tf32.tf32.f32 "
        "{%0,%1,%2,%3}, {%4,%5,%6,%7}, {%8,%9}, {%0,%1,%2,%3};"
        : "+f"(c[0]), "+f"(c[1]), "+f"(c[2]), "+f"(c[3])
        : "r"(a[0]), "r"(a[1]), "r"(a[2]), "r"(a[3]), "r"(b[0]), "r"(b[1]));
}

// ---------------- tf32 pre-conversion (W1, W2, x) ----------------
__global__ void convert_tf32(const float* __restrict__ W1,
                             const float* __restrict__ W2,
                             const float* __restrict__ x) {
    const size_t n1 = W1SZ / 4, n2 = W2SZ / 4, n3 = XSZ / 4;
    const size_t total = n1 + n2 + n3;
    size_t stride = (size_t)gridDim.x * blockDim.x;
    for (size_t i = (size_t)blockIdx.x * blockDim.x + threadIdx.x; i < total; i += stride) {
        const float4* src; float4* dst; size_t j;
        if (i < n1)            { src = (const float4*)W1; dst = (float4*)g_W1t; j = i; }
        else if (i < n1 + n2)  { src = (const float4*)W2; dst = (float4*)g_W2t; j = i - n1; }
        else                   { src = (const float4*)x;  dst = (float4*)g_xt;  j = i - n1 - n2; }
        float4 v = src[j];
        v.x = f2tf(v.x); v.y = f2tf(v.y); v.z = f2tf(v.z); v.w = f2tf(v.w);
        dst[j] = v;
    }
}

// ---------------- init ----------------
__global__ void init_kernel() {
    int t = threadIdx.x;
    if (t < E_) g_counts[t] = 0;
}

// ---------------- gate: one warp per token ----------------
__global__ void gate_kernel(const float* __restrict__ x,
                            const float* __restrict__ Wg,
                            const float* __restrict__ bg) {
    int warp = (blockIdx.x * blockDim.x + threadIdx.x) >> 5;
    int lane = threadIdx.x & 31;
    if (warp >= N_) return;
    const float* xr = x + (size_t)warp * D_;

    float acc[E_];
#pragma unroll
    for (int e = 0; e < E_; e++) acc[e] = 0.f;

    for (int d = lane; d < D_; d += 32) {
        float xv = xr[d];
        const float4* w = reinterpret_cast<const float4*>(Wg + (size_t)d * E_);
        float4 w0 = w[0], w1 = w[1];
        acc[0] += xv * w0.x; acc[1] += xv * w0.y;
        acc[2] += xv * w0.z; acc[3] += xv * w0.w;
        acc[4] += xv * w1.x; acc[5] += xv * w1.y;
        acc[6] += xv * w1.z; acc[7] += xv * w1.w;
    }
#pragma unroll
    for (int off = 16; off > 0; off >>= 1) {
#pragma unroll
        for (int e = 0; e < E_; e++)
            acc[e] += __shfl_down_sync(0xFFFFFFFFu, acc[e], off);
    }
    if (lane == 0) {
        float best = acc[0] + bg[0];
        int bi = 0;
#pragma unroll
        for (int e = 1; e < E_; e++) {
            float v = acc[e] + bg[e];
            if (v > best) { best = v; bi = e; }
        }
        int p = atomicAdd(&g_counts[bi], 1);
        g_expert[warp] = bi;
        g_pos[warp]    = p;
    }
}

// ---------------- exclusive scan of 8 counts ----------------
__global__ void scan_kernel() {
    if (threadIdx.x == 0) {
        int s = 0;
#pragma unroll
        for (int e = 0; e < E_; e++) { g_offsets[e] = s; s += g_counts[e]; }
    }
}

// ---------------- assign compacted rows ----------------
__global__ void assign_kernel() {
    int t = blockIdx.x * blockDim.x + threadIdx.x;
    if (t >= N_) return;
    int e = g_expert[t];
    int r = g_offsets[e] + g_pos[t];
    g_row2tok[r]    = t;
    g_rowexpert[r]  = e;
}

// =====================================================================
// GEMM1: H = tf32(relu(Xt[gather] @ W1t[e] + b1[e]))
// BM=128 BN=128 BK=16, 256 thr, 8 warps (4x2), warp tile 32x64 (2x8 MMA)
// All operands already tf32-rounded -> zero CVTs in the loop.
// =====================================================================
__global__ __launch_bounds__(256, 2)
void gemm1_tc(const float* __restrict__ b1) {
    const int e   = blockIdx.z;
    const int cnt = g_counts[e];
    const int m0  = blockIdx.y * BM;
    if (m0 >= cnt) return;
    const int off = g_offsets[e];
    const int n0  = blockIdx.x * BN;
    const float* Wb = g_W1t + (size_t)e * D_ * F_;

    __shared__ __align__(16) float As[2][BM][BK + 4];   // stride 20
    __shared__ __align__(16) float Bs[2][BK][BN + 8];   // stride 136

    const int tid  = threadIdx.x;
    const int lane = tid & 31;
    const int warp = tid >> 5;
    const int wm   = warp >> 1;
    const int wn   = warp & 1;

    const int arow0 = tid >> 2,           akc0 = (tid & 3) * 4;
    const int arow1 = (tid + 256) >> 2,   akc1 = ((tid + 256) & 3) * 4;
    const float* ap0 = g_xt + (size_t)g_row2tok[off + imin(m0 + arow0, cnt - 1)] * D_ + akc0;
    const float* ap1 = g_xt + (size_t)g_row2tok[off + imin(m0 + arow1, cnt - 1)] * D_ + akc1;
    const int bk0 = tid >> 5, bnc = (tid & 31) * 4;
    const int bk1 = bk0 + 8;
    const float* bp0 = Wb + (size_t)bk0 * F_ + n0 + bnc;
    const float* bp1 = Wb + (size_t)bk1 * F_ + n0 + bnc;

    float acc[2][8][4];
#pragma unroll
    for (int i = 0; i < 2; i++)
#pragma unroll
        for (int j = 0; j < 8; j++)
#pragma unroll
            for (int q = 0; q < 4; q++) acc[i][j][q] = 0.f;

    cp_async16(&As[0][arow0][akc0], ap0);
    cp_async16(&As[0][arow1][akc1], ap1);
    cp_async16(&Bs[0][bk0][bnc],    bp0);
    cp_async16(&Bs[0][bk1][bnc],    bp1);
    cp_commit();

    const int NK = D_ / BK;   // 32
    for (int it = 0; it < NK; ++it) {
        const int cur = it & 1;
        if (it + 1 < NK) {
            const int nxt = cur ^ 1;
            const int k0  = (it + 1) * BK;
            cp_async16(&As[nxt][arow0][akc0], ap0 + k0);
            cp_async16(&As[nxt][arow1][akc1], ap1 + k0);
            cp_async16(&Bs[nxt][bk0][bnc],    bp0 + (size_t)k0 * F_);
            cp_async16(&Bs[nxt][bk1][bnc],    bp1 + (size_t)k0 * F_);
            cp_commit();
            asm volatile("cp.async.wait_group 1;");
        } else {
            asm volatile("cp.async.wait_group 0;");
        }
        __syncthreads();

#pragma unroll
        for (int kk = 0; kk < 2; ++kk) {
            const int kb = kk * 8 + (lane & 3);
            uint32_t a[2][4], b[8][2];
#pragma unroll
            for (int mt = 0; mt < 2; ++mt) {
                const int r = wm * 32 + mt * 16 + (lane >> 2);
                a[mt][0] = __float_as_uint(As[cur][r][kb]);
                a[mt][1] = __float_as_uint(As[cur][r + 8][kb]);
                a[mt][2] = __float_as_uint(As[cur][r][kb + 4]);
                a[mt][3] = __float_as_uint(As[cur][r + 8][kb + 4]);
            }
#pragma unroll
            for (int nt = 0; nt < 8; ++nt) {
                const int c = wn * 64 + nt * 8 + (lane >> 2);
                b[nt][0] = __float_as_uint(Bs[cur][kb][c]);
                b[nt][1] = __float_as_uint(Bs[cur][kb + 4][c]);
            }
#pragma unroll
            for (int mt = 0; mt < 2; ++mt)
#pragma unroll
                for (int nt = 0; nt < 8; ++nt)
                    mma_tf32(acc[mt][nt], a[mt], b[nt]);
        }
        __syncthreads();
    }

    // epilogue: bias + relu + tf32-round -> g_H
    const float* b1e = b1 + (size_t)e * F_;
#pragma unroll
    for (int mt = 0; mt < 2; ++mt) {
        const int rbase = m0 + wm * 32 + mt * 16 + (lane >> 2);
#pragma unroll
        for (int half = 0; half < 2; ++half) {
            const int r = rbase + half * 8;
            if (r < cnt) {
                float* Hrow = g_H + (size_t)(off + r) * F_;
#pragma unroll
                for (int nt = 0; nt < 8; ++nt) {
                    const int c = n0 + wn * 64 + nt * 8 + (lane & 3) * 2;
                    float2 o;
                    o.x = f2tf(fmaxf(acc[mt][nt][half * 2 + 0] + b1e[c],     0.f));
                    o.y = f2tf(fmaxf(acc[mt][nt][half * 2 + 1] + b1e[c + 1], 0.f));
                    *reinterpret_cast<float2*>(Hrow + c) = o;
                }
            }
        }
    }
}

// =====================================================================
// GEMM2 (split-K=2): g_part[kp] = H[:, kp-half] @ W2t[e][kp-half]
// grid.x = 4 n-tiles * KSPLIT
// =====================================================================
__global__ __launch_bounds__(256, 2)
void gemm2_tc() {
    const int e   = blockIdx.z;
    const int cnt = g_counts[e];
    const int m0  = blockIdx.y * BM;
    if (m0 >= cnt) return;
    const int off = g_offsets[e];
    const int kp  = blockIdx.x >> 2;             // 0..KSPLIT-1
    const int n0  = (blockIdx.x & 3) * BN;
    const int kbase = kp * (F_ / KSPLIT);
    const float* Wb = g_W2t + (size_t)e * F_ * D_ + (size_t)kbase * D_;

    __shared__ __align__(16) float As[2][BM][BK + 4];
    __shared__ __align__(16) float Bs[2][BK][BN + 8];

    const int tid  = threadIdx.x;
    const int lane = tid & 31;
    const int warp = tid >> 5;
    const int wm   = warp >> 1;
    const int wn   = warp & 1;

    const int arow0 = tid >> 2,           akc0 = (tid & 3) * 4;
    const int arow1 = (tid + 256) >> 2,   akc1 = ((tid + 256) & 3) * 4;
    const float* ap0 = g_H + (size_t)(off + imin(m0 + arow0, cnt - 1)) * F_ + kbase + akc0;
    const float* ap1 = g_H + (size_t)(off + imin(m0 + arow1, cnt - 1)) * F_ + kbase + akc1;
    const int bk0 = tid >> 5, bnc = (tid & 31) * 4;
    const int bk1 = bk0 + 8;
    const float* bp0 = Wb + (size_t)bk0 * D_ + n0 + bnc;
    const float* bp1 = Wb + (size_t)bk1 * D_ + n0 + bnc;

    float acc[2][8][4];
#pragma unroll
    for (int i = 0; i < 2; i++)
#pragma unroll
        for (int j = 0; j < 8; j++)
#pragma unroll
            for (int q = 0; q < 4; q++) acc[i][j][q] = 0.f;

    cp_async16(&As[0][arow0][akc0], ap0);
    cp_async16(&As[0][arow1][akc1], ap1);
    cp_async16(&Bs[0][bk0][bnc],    bp0);
    cp_async16(&Bs[0][bk1][bnc],    bp1);
    cp_commit();

    const int NK = (F_ / KSPLIT) / BK;   // 64
    for (int it = 0; it < NK; ++it) {
        const int cur = it & 1;
        if (it + 1 < NK) {
            const int nxt = cur ^ 1;
            const int k0  = (it + 1) * BK;
            cp_async16(&As[nxt][arow0][akc0], ap0 + k0);
            cp_async16(&As[nxt][arow1][akc1], ap1 + k0);
            cp_async16(&Bs[nxt][bk0][bnc],    bp0 + (size_t)k0 * D_);
            cp_async16(&Bs[nxt][bk1][bnc],    bp1 + (size_t)k0 * D_);
            cp_commit();
            asm volatile("cp.async.wait_group 1;");
        } else {
            asm volatile("cp.async.wait_group 0;");
        }
        __syncthreads();

#pragma unroll
        for (int kk = 0; kk < 2; ++kk) {
            const int kb = kk * 8 + (lane & 3);
            uint32_t a[2][4], b[8][2];
#pragma unroll
            for (int mt = 0; mt < 2; ++mt) {
                const int r = wm * 32 + mt * 16 + (lane >> 2);
                a[mt][0] = __float_as_uint(As[cur][r][kb]);
                a[mt][1] = __float_as_uint(As[cur][r + 8][kb]);
                a[mt][2] = __float_as_uint(As[cur][r][kb + 4]);
                a[mt][3] = __float_as_uint(As[cur][r + 8][kb + 4]);
            }
#pragma unroll
            for (int nt = 0; nt < 8; ++nt) {
                const int c = wn * 64 + nt * 8 + (lane >> 2);
                b[nt][0] = __float_as_uint(Bs[cur][kb][c]);
                b[nt][1] = __float_as_uint(Bs[cur][kb + 4][c]);
            }
#pragma unroll
            for (int mt = 0; mt < 2; ++mt)
#pragma unroll
                for (int nt = 0; nt < 8; ++nt)
                    mma_tf32(acc[mt][nt], a[mt], b[nt]);
        }
        __syncthreads();
    }

    // epilogue: store partial (no bias) to g_part[kp]
    float* part = g_part[kp];
#pragma unroll
    for (int mt = 0; mt < 2; ++mt) {
        const int rbase = m0 + wm * 32 + mt * 16 + (lane >> 2);
#pragma unroll
        for (int half = 0; half < 2; ++half) {
            const int r = rbase + half * 8;
            if (r < cnt) {
                float* prow = part + (size_t)(off + r) * D_;
#pragma unroll
                for (int nt = 0; nt < 8; ++nt) {
                    const int c = n0 + wn * 64 + nt * 8 + (lane & 3) * 2;
                    float2 o;
                    o.x = acc[mt][nt][half * 2 + 0];
                    o.y = acc[mt][nt][half * 2 + 1];
                    *reinterpret_cast<float2*>(prow + c) = o;
                }
            }
        }
    }
}

// ---------------- reduce: out[tok] = part0 + part1 + b2[e] ----------------
__global__ void reduce_kernel(const float* __restrict__ b2,
                              float* __restrict__ out) {
    int idx = blockIdx.x * blockDim.x + threadIdx.x;      // float4 index
    const int rowq = D_ / 4;
    if (idx >= N_ * rowq) return;
    int r  = idx / rowq;
    int c4 = idx - r * rowq;
    int tok = g_row2tok[r];
    int e   = g_rowexpert[r];
    float4 p0 = reinterpret_cast<const float4*>(g_part[0])[(size_t)r * rowq + c4];
    float4 p1 = reinterpret_cast<const float4*>(g_part[1])[(size_t)r * rowq + c4];
    float4 bb = reinterpret_cast<const float4*>(b2 + (size_t)e * D_)[c4];
    float4 o;
    o.x = p0.x + p1.x + bb.x;
    o.y = p0.y + p1.y + bb.y;
    o.z = p0.z + p1.z + bb.z;
    o.w = p0.w + p1.w + bb.w;
    reinterpret_cast<float4*>(out)[(size_t)tok * rowq + c4] = o;
}

// ---------------- launch ----------------
extern "C" void kernel_launch(void* const* d_in, const int* in_sizes, int n_in,
                              void* d_out, int out_size) {
    const float* x  = (const float*)d_in[0];
    const float* Wg = (const float*)d_in[1];
    const float* bg = (const float*)d_in[2];
    const float* W1 = (const float*)d_in[3];
    const float* b1 = (const float*)d_in[4];
    const float* W2 = (const float*)d_in[5];
    const float* b2 = (const float*)d_in[6];
    float* out = (float*)d_out;

    convert_tf32<<<1184, 256>>>(W1, W2, x);
    init_kernel<<<1, 32>>>();
    gate_kernel<<<(N_ * 32) / 256, 256>>>(x, Wg, bg);
    scan_kernel<<<1, 32>>>();
    assign_kernel<<<N_ / 256, 256>>>();

    dim3 g1(F_ / BN, N_ / BM, E_);              // (16, 32, 8)
    gemm1_tc<<<g1, 256>>>(b1);

    dim3 g2((D_ / BN) * KSPLIT, N_ / BM, E_);   // (8, 32, 8)
    gemm2_tc<<<g2, 256>>>();

    reduce_kernel<<<(N_ * D_ / 4) / 256, 256>>>(b2, out);
}

// round 4
// speedup vs baseline: 3.5856x; 1.0749x over previous
#include <cuda_runtime.h>
#include <cstdint>

#define E_ 8
#define D_ 512
#define F_ 2048
#define N_ 4096

#define BM 128
#define BN 128
#define BK 16
#define KSPLIT 2

// dynamic SMEM layout (floats): A: 3 stages x 128 x 20 ; B: 3 stages x 16 x 136
#define A_STAGE 2560
#define B_BASE  7680
#define B_STAGE 2176
#define SMEM_FLOATS (B_BASE + 3 * B_STAGE)
#define SMEM_BYTES  (SMEM_FLOATS * 4)

#define SM_A(s, r, k) smem[(s) * A_STAGE + (r) * 20 + (k)]
#define SM_B(s, k, n) smem[B_BASE + (s) * B_STAGE + (k) * 136 + (n)]

#define W1SZ ((size_t)E_ * D_ * F_)
#define W2SZ ((size_t)E_ * F_ * D_)
#define XSZ  ((size_t)N_ * D_)

// ---------------- scratch (no allocations allowed) ----------------
__device__ int   g_counts[E_];
__device__ int   g_expert[N_];
__device__ int   g_pos[N_];
__device__ int   g_row2tok[N_];
__device__ int   g_rowexpert[N_];
__device__ __align__(16) float g_W1t[W1SZ];
__device__ __align__(16) float g_W2t[W2SZ];
__device__ __align__(16) float g_xt[XSZ];
__device__ __align__(16) float g_H[(size_t)N_ * F_];
__device__ __align__(16) float g_part[KSPLIT][(size_t)N_ * D_];

// ---------------- helpers ----------------
__device__ __forceinline__ int imin(int a, int b) { return a < b ? a : b; }

__device__ __forceinline__ void cp_async16(void* sm, const void* gm) {
    uint32_t s = (uint32_t)__cvta_generic_to_shared(sm);
    asm volatile("cp.async.cg.shared.global [%0], [%1], 16;" :: "r"(s), "l"(gm));
}
__device__ __forceinline__ void cp_commit() {
    asm volatile("cp.async.commit_group;");
}
__device__ __forceinline__ void cp_wait1() {
    asm volatile("cp.async.wait_group 1;");
}

__device__ __forceinline__ float f2tf(float f) {
    uint32_t r;
    asm("cvt.rna.tf32.f32 %0, %1;" : "=r"(r) : "f"(f));
    return __uint_as_float(r);
}

__device__ __forceinline__ void mma_tf32(float c[4], const uint32_t a[4], const uint32_t b[2]) {
    asm volatile(
        "mma.sync.aligned.m16n8k8.row.col.f32.tf32.tf32.f32 "
        "{%0,%1,%2,%3}, {%4,%5,%6,%7}, {%8,%9}, {%0,%1,%2,%3};"
        : "+f"(c[0]), "+f"(c[1]), "+f"(c[2]), "+f"(c[3])
        : "r"(a[0]), "r"(a[1]), "r"(a[2]), "r"(a[3]), "r"(b[0]), "r"(b[1]));
}

__device__ __forceinline__ int expert_off(int e) {
    int s = 0;
#pragma unroll
    for (int i = 0; i < E_; i++) if (i < e) s += g_counts[i];
    return s;
}

// ---------------- tf32 pre-conversion (W1, W2, x) + count init ----------------
__global__ void convert_tf32(const float* __restrict__ W1,
                             const float* __restrict__ W2,
                             const float* __restrict__ x) {
    if (blockIdx.x == 0 && threadIdx.x < E_) g_counts[threadIdx.x] = 0;
    const size_t n1 = W1SZ / 4, n2 = W2SZ / 4, n3 = XSZ / 4;
    const size_t total = n1 + n2 + n3;
    size_t stride = (size_t)gridDim.x * blockDim.x;
    for (size_t i = (size_t)blockIdx.x * blockDim.x + threadIdx.x; i < total; i += stride) {
        const float4* src; float4* dst; size_t j;
        if (i < n1)            { src = (const float4*)W1; dst = (float4*)g_W1t; j = i; }
        else if (i < n1 + n2)  { src = (const float4*)W2; dst = (float4*)g_W2t; j = i - n1; }
        else                   { src = (const float4*)x;  dst = (float4*)g_xt;  j = i - n1 - n2; }
        float4 v = src[j];
        v.x = f2tf(v.x); v.y = f2tf(v.y); v.z = f2tf(v.z); v.w = f2tf(v.w);
        dst[j] = v;
    }
}

// ---------------- gate: one warp per token ----------------
__global__ void gate_kernel(const float* __restrict__ x,
                            const float* __restrict__ Wg,
                            const float* __restrict__ bg) {
    int warp = (blockIdx.x * blockDim.x + threadIdx.x) >> 5;
    int lane = threadIdx.x & 31;
    if (warp >= N_) return;
    const float* xr = x + (size_t)warp * D_;

    float acc[E_];
#pragma unroll
    for (int e = 0; e < E_; e++) acc[e] = 0.f;

    for (int d = lane; d < D_; d += 32) {
        float xv = xr[d];
        const float4* w = reinterpret_cast<const float4*>(Wg + (size_t)d * E_);
        float4 w0 = w[0], w1 = w[1];
        acc[0] += xv * w0.x; acc[1] += xv * w0.y;
        acc[2] += xv * w0.z; acc[3] += xv * w0.w;
        acc[4] += xv * w1.x; acc[5] += xv * w1.y;
        acc[6] += xv * w1.z; acc[7] += xv * w1.w;
    }
#pragma unroll
    for (int off = 16; off > 0; off >>= 1) {
#pragma unroll
        for (int e = 0; e < E_; e++)
            acc[e] += __shfl_down_sync(0xFFFFFFFFu, acc[e], off);
    }
    if (lane == 0) {
        float best = acc[0] + bg[0];
        int bi = 0;
#pragma unroll
        for (int e = 1; e < E_; e++) {
            float v = acc[e] + bg[e];
            if (v > best) { best = v; bi = e; }
        }
        int p = atomicAdd(&g_counts[bi], 1);
        g_expert[warp] = bi;
        g_pos[warp]    = p;
    }
}

// ---------------- assign compacted rows (local scan of 8 counts) ----------------
__global__ void assign_kernel() {
    int t = blockIdx.x * blockDim.x + threadIdx.x;
    if (t >= N_) return;
    int e = g_expert[t];
    int r = expert_off(e) + g_pos[t];
    g_row2tok[r]   = t;
    g_rowexpert[r] = e;
}

// =====================================================================
// GEMM1: H = tf32(relu(Xt[gather] @ W1t[e] + b1[e]))
// 128 threads, 4 warps (2x2), warp tile 64x64 (4x8 m16n8k8 MMAs)
// 3-stage cp.async ring, ONE __syncthreads per k-iter.
// =====================================================================
__global__ __launch_bounds__(128, 2)
void gemm1_tc(const float* __restrict__ b1) {
    extern __shared__ float smem[];
    const int e   = blockIdx.z;
    const int cnt = g_counts[e];
    const int m0  = blockIdx.y * BM;
    if (m0 >= cnt) return;
    const int off = expert_off(e);
    const int n0  = blockIdx.x * BN;
    const float* Wb = g_W1t + (size_t)e * D_ * F_;

    const int tid  = threadIdx.x;
    const int lane = tid & 31;
    const int warp = tid >> 5;
    const int wm   = warp >> 1;
    const int wn   = warp & 1;

    // loaders: A 128x16 (512 x16B chunks), B 16x128 (512 chunks); 4 chunks each
    const int rbase = tid >> 2;            // 0..31
    const int kc    = (tid & 3) * 4;
    const int kb0   = tid >> 5;            // 0..3
    const int nc    = (tid & 31) * 4;

    const float* ap[4];
    const float* bp[4];
#pragma unroll
    for (int j = 0; j < 4; j++) {
        int rr = imin(m0 + rbase + 32 * j, cnt - 1);
        ap[j] = g_xt + (size_t)g_row2tok[off + rr] * D_ + kc;
        bp[j] = Wb + (size_t)(kb0 + 4 * j) * F_ + n0 + nc;
    }

    float acc[4][8][4];
#pragma unroll
    for (int i = 0; i < 4; i++)
#pragma unroll
        for (int j = 0; j < 8; j++)
#pragma unroll
            for (int q = 0; q < 4; q++) acc[i][j][q] = 0.f;

    // prologue: stages 0,1
#pragma unroll
    for (int s = 0; s < 2; s++) {
#pragma unroll
        for (int j = 0; j < 4; j++) {
            cp_async16(&SM_A(s, rbase + 32 * j, kc), ap[j] + s * BK);
            cp_async16(&SM_B(s, kb0 + 4 * j, nc), bp[j] + (size_t)s * BK * F_);
        }
        cp_commit();
    }

    const int NK = D_ / BK;   // 32
    for (int it = 0; it < NK; ++it) {
        cp_wait1();
        __syncthreads();
        if (it + 2 < NK) {
            const int s  = (it + 2) % 3;
            const int k0 = (it + 2) * BK;
#pragma unroll
            for (int j = 0; j < 4; j++) {
                cp_async16(&SM_A(s, rbase + 32 * j, kc), ap[j] + k0);
                cp_async16(&SM_B(s, kb0 + 4 * j, nc), bp[j] + (size_t)k0 * F_);
            }
        }
        cp_commit();   // empty groups in tail keep the wait invariant

        const int cur = it % 3;
#pragma unroll
        for (int kk = 0; kk < 2; ++kk) {
            const int kb = kk * 8 + (lane & 3);
            uint32_t a[4][4], b[8][2];
#pragma unroll
            for (int mt = 0; mt < 4; ++mt) {
                const int r = wm * 64 + mt * 16 + (lane >> 2);
                a[mt][0] = __float_as_uint(SM_A(cur, r,     kb));
                a[mt][1] = __float_as_uint(SM_A(cur, r + 8, kb));
                a[mt][2] = __float_as_uint(SM_A(cur, r,     kb + 4));
                a[mt][3] = __float_as_uint(SM_A(cur, r + 8, kb + 4));
            }
#pragma unroll
            for (int nt = 0; nt < 8; ++nt) {
                const int c = wn * 64 + nt * 8 + (lane >> 2);
                b[nt][0] = __float_as_uint(SM_B(cur, kb,     c));
                b[nt][1] = __float_as_uint(SM_B(cur, kb + 4, c));
            }
#pragma unroll
            for (int mt = 0; mt < 4; ++mt)
#pragma unroll
                for (int nt = 0; nt < 8; ++nt)
                    mma_tf32(acc[mt][nt], a[mt], b[nt]);
        }
    }

    // epilogue: bias + relu + tf32-round -> g_H
    const float* b1e = b1 + (size_t)e * F_;
#pragma unroll
    for (int mt = 0; mt < 4; ++mt) {
        const int rbase2 = m0 + wm * 64 + mt * 16 + (lane >> 2);
#pragma unroll
        for (int half = 0; half < 2; ++half) {
            const int r = rbase2 + half * 8;
            if (r < cnt) {
                float* Hrow = g_H + (size_t)(off + r) * F_;
#pragma unroll
                for (int nt = 0; nt < 8; ++nt) {
                    const int c = n0 + wn * 64 + nt * 8 + (lane & 3) * 2;
                    float2 o;
                    o.x = f2tf(fmaxf(acc[mt][nt][half * 2 + 0] + b1e[c],     0.f));
                    o.y = f2tf(fmaxf(acc[mt][nt][half * 2 + 1] + b1e[c + 1], 0.f));
                    *reinterpret_cast<float2*>(Hrow + c) = o;
                }
            }
        }
    }
}

// =====================================================================
// GEMM2 (split-K=2): g_part[kp] = H[:, kp-half] @ W2t[e][kp-half]
// =====================================================================
__global__ __launch_bounds__(128, 2)
void gemm2_tc() {
    extern __shared__ float smem[];
    const int e   = blockIdx.z;
    const int cnt = g_counts[e];
    const int m0  = blockIdx.y * BM;
    if (m0 >= cnt) return;
    const int off = expert_off(e);
    const int kp  = blockIdx.x >> 2;
    const int n0  = (blockIdx.x & 3) * BN;
    const int kbase = kp * (F_ / KSPLIT);
    const float* Wb = g_W2t + (size_t)e * F_ * D_ + (size_t)kbase * D_;

    const int tid  = threadIdx.x;
    const int lane = tid & 31;
    const int warp = tid >> 5;
    const int wm   = warp >> 1;
    const int wn   = warp & 1;

    const int rbase = tid >> 2;
    const int kc    = (tid & 3) * 4;
    const int kb0   = tid >> 5;
    const int nc    = (tid & 31) * 4;

    const float* ap[4];
    const float* bp[4];
#pragma unroll
    for (int j = 0; j < 4; j++) {
        int rr = imin(m0 + rbase + 32 * j, cnt - 1);
        ap[j] = g_H + (size_t)(off + rr) * F_ + kbase + kc;
        bp[j] = Wb + (size_t)(kb0 + 4 * j) * D_ + n0 + nc;
    }

    float acc[4][8][4];
#pragma unroll
    for (int i = 0; i < 4; i++)
#pragma unroll
        for (int j = 0; j < 8; j++)
#pragma unroll
            for (int q = 0; q < 4; q++) acc[i][j][q] = 0.f;

#pragma unroll
    for (int s = 0; s < 2; s++) {
#pragma unroll
        for (int j = 0; j < 4; j++) {
            cp_async16(&SM_A(s, rbase + 32 * j, kc), ap[j] + s * BK);
            cp_async16(&SM_B(s, kb0 + 4 * j, nc), bp[j] + (size_t)s * BK * D_);
        }
        cp_commit();
    }

    const int NK = (F_ / KSPLIT) / BK;   // 64
    for (int it = 0; it < NK; ++it) {
        cp_wait1();
        __syncthreads();
        if (it + 2 < NK) {
            const int s  = (it + 2) % 3;
            const int k0 = (it + 2) * BK;
#pragma unroll
            for (int j = 0; j < 4; j++) {
                cp_async16(&SM_A(s, rbase + 32 * j, kc), ap[j] + k0);
                cp_async16(&SM_B(s, kb0 + 4 * j, nc), bp[j] + (size_t)k0 * D_);
            }
        }
        cp_commit();

        const int cur = it % 3;
#pragma unroll
        for (int kk = 0; kk < 2; ++kk) {
            const int kb = kk * 8 + (lane & 3);
            uint32_t a[4][4], b[8][2];
#pragma unroll
            for (int mt = 0; mt < 4; ++mt) {
                const int r = wm * 64 + mt * 16 + (lane >> 2);
                a[mt][0] = __float_as_uint(SM_A(cur, r,     kb));
                a[mt][1] = __float_as_uint(SM_A(cur, r + 8, kb));
                a[mt][2] = __float_as_uint(SM_A(cur, r,     kb + 4));
                a[mt][3] = __float_as_uint(SM_A(cur, r + 8, kb + 4));
            }
#pragma unroll
            for (int nt = 0; nt < 8; ++nt) {
                const int c = wn * 64 + nt * 8 + (lane >> 2);
                b[nt][0] = __float_as_uint(SM_B(cur, kb,     c));
                b[nt][1] = __float_as_uint(SM_B(cur, kb + 4, c));
            }
#pragma unroll
            for (int mt = 0; mt < 4; ++mt)
#pragma unroll
                for (int nt = 0; nt < 8; ++nt)
                    mma_tf32(acc[mt][nt], a[mt], b[nt]);
        }
    }

    float* part = g_part[kp];
#pragma unroll
    for (int mt = 0; mt < 4; ++mt) {
        const int rbase2 = m0 + wm * 64 + mt * 16 + (lane >> 2);
#pragma unroll
        for (int half = 0; half < 2; ++half) {
            const int r = rbase2 + half * 8;
            if (r < cnt) {
                float* prow = part + (size_t)(off + r) * D_;
#pragma unroll
                for (int nt = 0; nt < 8; ++nt) {
                    const int c = n0 + wn * 64 + nt * 8 + (lane & 3) * 2;
                    float2 o;
                    o.x = acc[mt][nt][half * 2 + 0];
                    o.y = acc[mt][nt][half * 2 + 1];
                    *reinterpret_cast<float2*>(prow + c) = o;
                }
            }
        }
    }
}

// ---------------- reduce: out[tok] = part0 + part1 + b2[e] ----------------
__global__ void reduce_kernel(const float* __restrict__ b2,
                              float* __restrict__ out) {
    int idx = blockIdx.x * blockDim.x + threadIdx.x;
    const int rowq = D_ / 4;
    if (idx >= N_ * rowq) return;
    int r  = idx / rowq;
    int c4 = idx - r * rowq;
    int tok = g_row2tok[r];
    int e   = g_rowexpert[r];
    float4 p0 = reinterpret_cast<const float4*>(g_part[0])[(size_t)r * rowq + c4];
    float4 p1 = reinterpret_cast<const float4*>(g_part[1])[(size_t)r * rowq + c4];
    float4 bb = reinterpret_cast<const float4*>(b2 + (size_t)e * D_)[c4];
    float4 o;
    o.x = p0.x + p1.x + bb.x;
    o.y = p0.y + p1.y + bb.y;
    o.z = p0.z + p1.z + bb.z;
    o.w = p0.w + p1.w + bb.w;
    reinterpret_cast<float4*>(out)[(size_t)tok * rowq + c4] = o;
}

// ---------------- launch ----------------
extern "C" void kernel_launch(void* const* d_in, const int* in_sizes, int n_in,
                              void* d_out, int out_size) {
    const float* x  = (const float*)d_in[0];
    const float* Wg = (const float*)d_in[1];
    const float* bg = (const float*)d_in[2];
    const float* W1 = (const float*)d_in[3];
    const float* b1 = (const float*)d_in[4];
    const float* W2 = (const float*)d_in[5];
    const float* b2 = (const float*)d_in[6];
    float* out = (float*)d_out;

    cudaFuncSetAttribute(gemm1_tc, cudaFuncAttributeMaxDynamicSharedMemorySize, SMEM_BYTES);
    cudaFuncSetAttribute(gemm2_tc, cudaFuncAttributeMaxDynamicSharedMemorySize, SMEM_BYTES);

    convert_tf32<<<1184, 256>>>(W1, W2, x);
    gate_kernel<<<(N_ * 32) / 256, 256>>>(x, Wg, bg);
    assign_kernel<<<N_ / 256, 256>>>();

    dim3 g1(F_ / BN, N_ / BM, E_);              // (16, 32, 8)
    gemm1_tc<<<g1, 128, SMEM_BYTES>>>(b1);

    dim3 g2((D_ / BN) * KSPLIT, N_ / BM, E_);   // (8, 32, 8)
    gemm2_tc<<<g2, 128, SMEM_BYTES>>>();

    reduce_kernel<<<(N_ * D_ / 4) / 256, 256>>>(b2, out);
}